// round 2
// baseline (speedup 1.0000x reference)
#include <cuda_runtime.h>

// Multi-scale morphological closing, [4,8,256,256] fp32 -> [4,8,4,256,256].
// closing_s = erosion_s(dilation_s(x)), separable h then v per op.
// SE_s[j] = j^2/(4*t_s), t_s = 4^s, half-width w_s = 4*2^s, weighted by se_coef.
//
// Round-2 structure: 4 fused stage kernels (all scales per launch),
// register-resident windows, symmetric-pair trick:
//   max_j v[x+j] - kc*j^2 = max_d fmaf(-kc, d*d, max(v[x-d], v[x+d]))
// which is bit-exact vs the reference (monotone max commutes with the add
// under round-to-nearest; with c=0.5 all penalty products are exact anyway).

namespace {
constexpr int IMGS = 32;     // B*C
constexpr int H    = 256;
constexpr int W    = 256;
constexpr int NPIX = H * W;
constexpr int NTOT = IMGS * NPIX;
constexpr int K    = 8;      // outputs per thread (both passes)
constexpr int ROWS = 8;      // rows per block in h-pass
constexpr int SWMAX = 32;
}

// per-scale ping-pong scratch (2 x 32 MB) — static, no allocation
__device__ float g_t1[4][NTOT];
__device__ float g_t2[4][NTOT];

// ---------------------------------------------------------------------------
// Horizontal pass body: block = 256 thr = 8 rows x (32 lanes x 8 outputs).
// Row staged in smem with sentinel halo; window pulled into registers via
// aligned float4 LDS; symmetric-pair inner loop.
// ---------------------------------------------------------------------------
template<int SW, bool MX>
__device__ __forceinline__ void hpass_do(
    const float* __restrict__ in, long istr,
    float* __restrict__ out, long ostr,
    float kc, int inner, float (*sm)[W + 2 * SWMAX])
{
    constexpr int PADW = W + 2 * SW;
    constexpr float BIG = MX ? -1e9f : 1e9f;
    const float kcs = MX ? -kc : kc;

    const int img = inner >> 5;           // H/ROWS = 32 blocks per image
    const int rb  = inner & 31;
    const float* src = in + (long)img * istr + (long)(rb * ROWS) * W;

    for (int i = threadIdx.x; i < ROWS * PADW; i += 256) {
        const int r = i / PADW;
        const int p = i - r * PADW;
        const int x = p - SW;
        sm[r][p] = ((unsigned)x < (unsigned)W) ? src[r * W + x] : BIG;
    }
    __syncthreads();

    const int r    = threadIdx.x >> 5;    // warp per row
    const int lane = threadIdx.x & 31;
    const int x0   = lane * K;

    float wv[2 * SW + K];
    const float4* wp = reinterpret_cast<const float4*>(&sm[r][x0]);  // p=x0 <-> x=x0-SW
    #pragma unroll
    for (int i = 0; i < (2 * SW + K) / 4; ++i) {
        const float4 v = wp[i];
        wv[4 * i + 0] = v.x; wv[4 * i + 1] = v.y;
        wv[4 * i + 2] = v.z; wv[4 * i + 3] = v.w;
    }

    float acc[K];
    #pragma unroll
    for (int k = 0; k < K; ++k) acc[k] = wv[SW + k];     // d = 0, penalty 0

    #pragma unroll
    for (int d = 1; d <= SW; ++d) {
        const float dd = (float)(d * d);                 // compile-time imm
        #pragma unroll
        for (int k = 0; k < K; ++k) {
            const float a = wv[SW + k - d], b = wv[SW + k + d];
            const float m = MX ? fmaxf(a, b) : fminf(a, b);
            const float cand = fmaf(kcs, dd, m);
            acc[k] = MX ? fmaxf(acc[k], cand) : fminf(acc[k], cand);
        }
    }

    float* dst = out + (long)img * ostr + (long)(rb * ROWS + r) * W + x0;
    #pragma unroll
    for (int k = 0; k < K; ++k) dst[k] = acc[k];
    __syncthreads();   // smem reuse safety (single use per block, but cheap)
}

// ---------------------------------------------------------------------------
// Vertical pass body: block = 256 thr spanning full row width (coalesced),
// each thread 8 consecutive rows of one column; register window with a
// uniform interior fast-path (no guards) and a guarded edge path.
// ---------------------------------------------------------------------------
template<int SW, bool MX>
__device__ __forceinline__ void vpass_do(
    const float* __restrict__ in, long istr,
    float* __restrict__ out, long ostr,
    float kc, int inner)
{
    constexpr float BIG = MX ? -1e9f : 1e9f;
    const float kcs = MX ? -kc : kc;

    const int img = inner >> 5;           // H/K = 32 blocks per image
    const int yb  = inner & 31;
    const int x   = threadIdx.x;
    const int y0  = yb * K;
    const float* base = in + (long)img * istr + x;

    float wv[2 * SW + K];
    if (y0 >= SW && y0 + K + SW <= H) {   // uniform per block
        #pragma unroll
        for (int i = 0; i < 2 * SW + K; ++i)
            wv[i] = base[(long)(y0 - SW + i) * W];
    } else {
        #pragma unroll
        for (int i = 0; i < 2 * SW + K; ++i) {
            const int y = y0 - SW + i;
            wv[i] = ((unsigned)y < (unsigned)H) ? base[(long)y * W] : BIG;
        }
    }

    float acc[K];
    #pragma unroll
    for (int k = 0; k < K; ++k) acc[k] = wv[SW + k];

    #pragma unroll
    for (int d = 1; d <= SW; ++d) {
        const float dd = (float)(d * d);
        #pragma unroll
        for (int k = 0; k < K; ++k) {
            const float a = wv[SW + k - d], b = wv[SW + k + d];
            const float m = MX ? fmaxf(a, b) : fminf(a, b);
            const float cand = fmaf(kcs, dd, m);
            acc[k] = MX ? fmaxf(acc[k], cand) : fminf(acc[k], cand);
        }
    }

    float* dst = out + (long)img * ostr + (long)y0 * W + x;
    #pragma unroll
    for (int k = 0; k < K; ++k) dst[k * W] = acc[k];
}

// ---------------------------------------------------------------------------
// Fused stage kernels: grid = 4 * 1024 blocks; scale = blockIdx.x & 3
// (round-robin for load balance), inner = blockIdx.x >> 2.
// ---------------------------------------------------------------------------
template<bool MX>
__global__ void __launch_bounds__(256, 2) hstage_k(
    const float* i0, const float* i1, const float* i2, const float* i3,
    float* o0, float* o1, float* o2, float* o3,
    long istr, long ostr, const float* __restrict__ sc)
{
    __shared__ __align__(16) float sm[ROWS][W + 2 * SWMAX];
    const float c = *sc;
    const int sid   = blockIdx.x & 3;
    const int inner = blockIdx.x >> 2;
    switch (sid) {
        case 0: hpass_do< 4, MX>(i0, istr, o0, ostr, c * 0.25f,       inner, sm); break;
        case 1: hpass_do< 8, MX>(i1, istr, o1, ostr, c * 0.0625f,     inner, sm); break;
        case 2: hpass_do<16, MX>(i2, istr, o2, ostr, c * 0.015625f,   inner, sm); break;
        default:hpass_do<32, MX>(i3, istr, o3, ostr, c * 0.00390625f, inner, sm); break;
    }
}

template<bool MX>
__global__ void __launch_bounds__(256, 2) vstage_k(
    const float* i0, const float* i1, const float* i2, const float* i3,
    float* o0, float* o1, float* o2, float* o3,
    long istr, long ostr, const float* __restrict__ sc)
{
    const float c = *sc;
    const int sid   = blockIdx.x & 3;
    const int inner = blockIdx.x >> 2;
    switch (sid) {
        case 0: vpass_do< 4, MX>(i0, istr, o0, ostr, c * 0.25f,       inner); break;
        case 1: vpass_do< 8, MX>(i1, istr, o1, ostr, c * 0.0625f,     inner); break;
        case 2: vpass_do<16, MX>(i2, istr, o2, ostr, c * 0.015625f,   inner); break;
        default:vpass_do<32, MX>(i3, istr, o3, ostr, c * 0.00390625f, inner); break;
    }
}

// ---------------------------------------------------------------------------
extern "C" void kernel_launch(void* const* d_in, const int* in_sizes, int n_in,
                              void* d_out, int out_size)
{
    const float* in = (const float*)d_in[0];
    const float* sc = (const float*)d_in[1];
    if (n_in >= 2 && in_sizes[0] == 1) {            // defensive: order swap
        in = (const float*)d_in[1];
        sc = (const float*)d_in[0];
    }
    float* out = (float*)d_out;

    float (*t1)[NTOT] = nullptr;
    float (*t2)[NTOT] = nullptr;
    cudaGetSymbolAddress((void**)&t1, g_t1);
    cudaGetSymbolAddress((void**)&t2, g_t2);

    const int grid = 4 * IMGS * (H / ROWS);   // 4096 blocks
    const long S = NPIX;

    // stage 1: horizontal dilation (input -> t1)
    hstage_k<true><<<grid, 256>>>(in, in, in, in,
                                  t1[0], t1[1], t1[2], t1[3], S, S, sc);
    // stage 2: vertical dilation (t1 -> t2)
    vstage_k<true><<<grid, 256>>>(t1[0], t1[1], t1[2], t1[3],
                                  t2[0], t2[1], t2[2], t2[3], S, S, sc);
    // stage 3: horizontal erosion (t2 -> t1)
    hstage_k<false><<<grid, 256>>>(t2[0], t2[1], t2[2], t2[3],
                                   t1[0], t1[1], t1[2], t1[3], S, S, sc);
    // stage 4: vertical erosion (t1 -> out slices, [B,C,S,H,W])
    vstage_k<false><<<grid, 256>>>(t1[0], t1[1], t1[2], t1[3],
                                   out + 0L * NPIX, out + 1L * NPIX,
                                   out + 2L * NPIX, out + 3L * NPIX,
                                   S, 4L * NPIX, sc);

    (void)out_size;
}

// round 3
// speedup vs baseline: 1.4525x; 1.4525x over previous
#include <cuda_runtime.h>

// Multi-scale morphological closing, [4,8,256,256] fp32 -> [4,8,4,256,256].
// closing_s = erosion_s(dilation_s(x)), separable h then v per op.
// SE_s[j] = j^2/(4*t_s), t_s = 4^s, half-width SW_s = 4*2^s, weight se_coef.
// kc = c/(4*t_s) = 4c/SW^2 (exact power-of-two scale for these SW).
//
// Round-3: per-scale specialized kernels (register budget matches scale),
// 4 independent scale-chains run CONCURRENTLY via stream fork-join under
// graph capture. Symmetric-pair inner loop:
//   max_j v[x+j] - kc*j^2 = max_d fmaf(-kc, d*d, max(v[x-d], v[x+d]))
// (bit-exact: RN max/min commute with the monotone add).

namespace {
constexpr int IMGS = 32;     // B*C
constexpr int H    = 256;
constexpr int W    = 256;
constexpr int NPIX = H * W;
constexpr int NTOT = IMGS * NPIX;
constexpr int K    = 8;      // outputs per thread (both passes)
constexpr int ROWS = 8;      // rows per block in h-pass
}

// per-scale ping-pong scratch — static, no allocation
__device__ float g_t1[4][NTOT];
__device__ float g_t2[4][NTOT];

// ---------------------------------------------------------------------------
// Horizontal pass: block = 256 thr = 8 rows x (32 lanes x 8 outputs).
// Row staged in smem with sentinel halo, window pulled to registers (LDS.128).
// ---------------------------------------------------------------------------
template<int SW, bool MX>
__global__ void __launch_bounds__(256) hk(
    const float* __restrict__ in,
    float* __restrict__ out, long ostr,
    const float* __restrict__ sc)
{
    constexpr int PADW = W + 2 * SW;
    constexpr float BIG = MX ? -1e9f : 1e9f;
    const float kc  = (*sc) * (4.0f / (float)(SW * SW));
    const float kcs = MX ? -kc : kc;

    __shared__ __align__(16) float sm[ROWS][PADW];

    const int img = blockIdx.x >> 5;          // 32 row-blocks per image
    const int rb  = blockIdx.x & 31;
    const float* src = in + (long)img * NPIX + (long)(rb * ROWS) * W;

    #pragma unroll
    for (int i = threadIdx.x; i < ROWS * PADW; i += 256) {
        const int r = i / PADW;
        const int p = i - r * PADW;
        const int x = p - SW;
        sm[r][p] = ((unsigned)x < (unsigned)W) ? src[r * W + x] : BIG;
    }
    __syncthreads();

    const int r    = threadIdx.x >> 5;        // warp per row
    const int lane = threadIdx.x & 31;
    const int x0   = lane * K;

    float wv[2 * SW + K];
    const float4* wp = reinterpret_cast<const float4*>(&sm[r][x0]);
    #pragma unroll
    for (int i = 0; i < (2 * SW + K) / 4; ++i) {
        const float4 v = wp[i];
        wv[4 * i + 0] = v.x; wv[4 * i + 1] = v.y;
        wv[4 * i + 2] = v.z; wv[4 * i + 3] = v.w;
    }

    float acc[K];
    #pragma unroll
    for (int k = 0; k < K; ++k) acc[k] = wv[SW + k];      // d = 0

    #pragma unroll
    for (int d = 1; d <= SW; ++d) {
        const float dd = (float)(d * d);                  // imm
        #pragma unroll
        for (int k = 0; k < K; ++k) {
            const float a = wv[SW + k - d], b = wv[SW + k + d];
            const float m = MX ? fmaxf(a, b) : fminf(a, b);
            const float cand = fmaf(kcs, dd, m);
            acc[k] = MX ? fmaxf(acc[k], cand) : fminf(acc[k], cand);
        }
    }

    float* dst = out + (long)img * ostr + (long)(rb * ROWS + r) * W + x0;
    #pragma unroll
    for (int k = 0; k < K; ++k) dst[k] = acc[k];
}

// ---------------------------------------------------------------------------
// Vertical pass: block = 256 thr spanning full row width (coalesced),
// each thread 8 consecutive rows of one column, register window.
// ---------------------------------------------------------------------------
template<int SW, bool MX>
__global__ void __launch_bounds__(256) vk(
    const float* __restrict__ in,
    float* __restrict__ out, long ostr,
    const float* __restrict__ sc)
{
    constexpr float BIG = MX ? -1e9f : 1e9f;
    const float kc  = (*sc) * (4.0f / (float)(SW * SW));
    const float kcs = MX ? -kc : kc;

    const int img = blockIdx.x >> 5;          // H/K = 32 blocks per image
    const int yb  = blockIdx.x & 31;
    const int x   = threadIdx.x;
    const int y0  = yb * K;
    const float* base = in + (long)img * NPIX + x;

    float wv[2 * SW + K];
    if (y0 >= SW && y0 + K + SW <= H) {       // uniform per block
        #pragma unroll
        for (int i = 0; i < 2 * SW + K; ++i)
            wv[i] = base[(long)(y0 - SW + i) * W];
    } else {
        #pragma unroll
        for (int i = 0; i < 2 * SW + K; ++i) {
            const int y = y0 - SW + i;
            wv[i] = ((unsigned)y < (unsigned)H) ? base[(long)y * W] : BIG;
        }
    }

    float acc[K];
    #pragma unroll
    for (int k = 0; k < K; ++k) acc[k] = wv[SW + k];

    #pragma unroll
    for (int d = 1; d <= SW; ++d) {
        const float dd = (float)(d * d);
        #pragma unroll
        for (int k = 0; k < K; ++k) {
            const float a = wv[SW + k - d], b = wv[SW + k + d];
            const float m = MX ? fmaxf(a, b) : fminf(a, b);
            const float cand = fmaf(kcs, dd, m);
            acc[k] = MX ? fmaxf(acc[k], cand) : fminf(acc[k], cand);
        }
    }

    float* dst = out + (long)img * ostr + (long)y0 * W + x;
    #pragma unroll
    for (int k = 0; k < K; ++k) dst[k * W] = acc[k];
}

// ---------------------------------------------------------------------------
template<int SW>
static void run_chain(cudaStream_t st, const float* in, float* t1, float* t2,
                      float* out_slice, const float* sc)
{
    const int grid = IMGS * (H / ROWS);       // 1024
    hk<SW, true ><<<grid, 256, 0, st>>>(in, t1, NPIX, sc);
    vk<SW, true ><<<grid, 256, 0, st>>>(t1, t2, NPIX, sc);
    hk<SW, false><<<grid, 256, 0, st>>>(t2, t1, NPIX, sc);
    vk<SW, false><<<grid, 256, 0, st>>>(t1, out_slice, 4L * NPIX, sc);
}

// side streams/events for concurrent chains (host objects; created once on
// the first, non-capturing, correctness call — no device allocation)
static cudaStream_t g_st[3];
static cudaEvent_t  g_fork, g_join[3];
static bool g_ready = false;

extern "C" void kernel_launch(void* const* d_in, const int* in_sizes, int n_in,
                              void* d_out, int out_size)
{
    const float* in = (const float*)d_in[0];
    const float* sc = (const float*)d_in[1];
    if (n_in >= 2 && in_sizes[0] == 1) {      // defensive: order swap
        in = (const float*)d_in[1];
        sc = (const float*)d_in[0];
    }
    float* out = (float*)d_out;

    if (!g_ready) {
        for (int i = 0; i < 3; ++i)
            cudaStreamCreateWithFlags(&g_st[i], cudaStreamNonBlocking);
        cudaEventCreateWithFlags(&g_fork, cudaEventDisableTiming);
        for (int i = 0; i < 3; ++i)
            cudaEventCreateWithFlags(&g_join[i], cudaEventDisableTiming);
        g_ready = true;
    }

    float (*t1)[NTOT] = nullptr;
    float (*t2)[NTOT] = nullptr;
    cudaGetSymbolAddress((void**)&t1, g_t1);
    cudaGetSymbolAddress((void**)&t2, g_t2);

    // fork: side streams join the capture graph via the fork event
    cudaEventRecord(g_fork, 0);
    for (int i = 0; i < 3; ++i) cudaStreamWaitEvent(g_st[i], g_fork, 0);

    // longest chain (SW=32) on the main stream; others on side streams
    run_chain<32>(0,       in, t1[3], t2[3], out + 3L * NPIX, sc);
    run_chain<16>(g_st[0], in, t1[2], t2[2], out + 2L * NPIX, sc);
    run_chain< 8>(g_st[1], in, t1[1], t2[1], out + 1L * NPIX, sc);
    run_chain< 4>(g_st[2], in, t1[0], t2[0], out + 0L * NPIX, sc);

    // join
    for (int i = 0; i < 3; ++i) {
        cudaEventRecord(g_join[i], g_st[i]);
        cudaStreamWaitEvent(0, g_join[i], 0);
    }

    (void)out_size;
}